// round 2
// baseline (speedup 1.0000x reference)
#include <cuda_runtime.h>
#include <math.h>

#define BATCH 4
#define SEQ   2048
#define DIM   1024
#define NHEAD 16
#define DH    64
#define NROWS (BATCH*SEQ)   // 8192

// ---------------- scratch (device globals: allocation-free rule) ----------------
__device__ float g_Q[(size_t)NROWS * DIM];
__device__ float g_K[(size_t)NROWS * DIM];
__device__ float g_V[(size_t)NROWS * DIM];
__device__ float g_O[(size_t)NROWS * DIM];
__device__ float g_cos[SEQ * 32];
__device__ float g_sin[SEQ * 32];

// ---------------- RoPE table ----------------
__global__ void rope_table_kernel(const int* __restrict__ pos)
{
    int idx = blockIdx.x * blockDim.x + threadIdx.x;
    if (idx >= SEQ * 32) return;
    int s = idx >> 5;
    int p = idx & 31;
    float inv = powf(10000.0f, -(float)(2 * p) / (float)DH);
    float ang = (float)pos[s] * inv;
    float sv, cv;
    sincosf(ang, &sv, &cv);
    g_cos[idx] = cv;
    g_sin[idx] = sv;
}

// ---------------- SGEMM: C[i,j] = sum_d X[i,d] * W[j,d]  (both K-major) ----------------
// MODE: 0 -> C=g_Q (RoPE), 1 -> C=g_K (RoPE), 2 -> C=g_V, 3 -> X=g_O, C=Cout (out proj)
#define BM 128
#define BN 128
#define BK 16

template<int MODE>
__global__ void __launch_bounds__(256) gemm_kernel(const float* __restrict__ Xin,
                                                   const float* __restrict__ W,
                                                   float* __restrict__ Cout)
{
    const float* X = (MODE == 3) ? g_O : Xin;
    float* C = (MODE == 0) ? g_Q : (MODE == 1) ? g_K : (MODE == 2) ? g_V : Cout;

    __shared__ float Xs[BK][BM];
    __shared__ float Ws[BK][BN];

    const int tid  = threadIdx.x;
    const int row0 = blockIdx.y * BM;
    const int col0 = blockIdx.x * BN;
    const int tx   = tid & 15;
    const int ty   = tid >> 4;
    const int lrow = tid >> 2;         // 0..63
    const int lkq  = (tid & 3) * 4;    // 0,4,8,12

    float4 xa[2], wa[2];
    float acc[8][8];
    #pragma unroll
    for (int i = 0; i < 8; i++)
        #pragma unroll
        for (int j = 0; j < 8; j++)
            acc[i][j] = 0.0f;

    // prologue: load + store tile 0
    #pragma unroll
    for (int it = 0; it < 2; it++) {
        int r = lrow + it * 64;
        xa[it] = *(const float4*)(X + (size_t)(row0 + r) * DIM + lkq);
        wa[it] = *(const float4*)(W + (size_t)(col0 + r) * DIM + lkq);
    }
    #pragma unroll
    for (int it = 0; it < 2; it++) {
        int r = lrow + it * 64;
        Xs[lkq + 0][r] = xa[it].x; Xs[lkq + 1][r] = xa[it].y;
        Xs[lkq + 2][r] = xa[it].z; Xs[lkq + 3][r] = xa[it].w;
        Ws[lkq + 0][r] = wa[it].x; Ws[lkq + 1][r] = wa[it].y;
        Ws[lkq + 2][r] = wa[it].z; Ws[lkq + 3][r] = wa[it].w;
    }
    __syncthreads();

    const int NKT = DIM / BK;  // 64
    for (int kt = 0; kt < NKT; kt++) {
        if (kt + 1 < NKT) {
            int k0 = (kt + 1) * BK;
            #pragma unroll
            for (int it = 0; it < 2; it++) {
                int r = lrow + it * 64;
                xa[it] = *(const float4*)(X + (size_t)(row0 + r) * DIM + k0 + lkq);
                wa[it] = *(const float4*)(W + (size_t)(col0 + r) * DIM + k0 + lkq);
            }
        }
        #pragma unroll
        for (int k = 0; k < BK; k++) {
            float a[8], b[8];
            float4 t;
            t = *(const float4*)&Xs[k][ty * 4];       a[0]=t.x; a[1]=t.y; a[2]=t.z; a[3]=t.w;
            t = *(const float4*)&Xs[k][64 + ty * 4];  a[4]=t.x; a[5]=t.y; a[6]=t.z; a[7]=t.w;
            t = *(const float4*)&Ws[k][tx * 4];       b[0]=t.x; b[1]=t.y; b[2]=t.z; b[3]=t.w;
            t = *(const float4*)&Ws[k][64 + tx * 4];  b[4]=t.x; b[5]=t.y; b[6]=t.z; b[7]=t.w;
            #pragma unroll
            for (int i = 0; i < 8; i++)
                #pragma unroll
                for (int j = 0; j < 8; j++)
                    acc[i][j] += a[i] * b[j];
        }
        __syncthreads();
        if (kt + 1 < NKT) {
            #pragma unroll
            for (int it = 0; it < 2; it++) {
                int r = lrow + it * 64;
                Xs[lkq + 0][r] = xa[it].x; Xs[lkq + 1][r] = xa[it].y;
                Xs[lkq + 2][r] = xa[it].z; Xs[lkq + 3][r] = xa[it].w;
                Ws[lkq + 0][r] = wa[it].x; Ws[lkq + 1][r] = wa[it].y;
                Ws[lkq + 2][r] = wa[it].z; Ws[lkq + 3][r] = wa[it].w;
            }
            __syncthreads();
        }
    }

    // epilogue
    #pragma unroll
    for (int i = 0; i < 8; i++) {
        int r = row0 + ((i < 4) ? (ty * 4 + i) : (64 + ty * 4 + (i - 4)));
        size_t rowoff = (size_t)r * DIM;
        if (MODE <= 1) {
            int s = r & (SEQ - 1);
            #pragma unroll
            for (int jh = 0; jh < 2; jh++) {
                int cbase = col0 + ((jh == 0) ? (tx * 4) : (64 + tx * 4));
                int jb = jh * 4;
                float4 ov;
                {
                    int p = (cbase & 63) >> 1;
                    float cv = g_cos[s * 32 + p], sv = g_sin[s * 32 + p];
                    float t1 = acc[i][jb + 0], t2 = acc[i][jb + 1];
                    ov.x = t1 * cv - t2 * sv;
                    ov.y = t1 * sv + t2 * cv;
                }
                {
                    int p = ((cbase + 2) & 63) >> 1;
                    float cv = g_cos[s * 32 + p], sv = g_sin[s * 32 + p];
                    float t1 = acc[i][jb + 2], t2 = acc[i][jb + 3];
                    ov.z = t1 * cv - t2 * sv;
                    ov.w = t1 * sv + t2 * cv;
                }
                *(float4*)(C + rowoff + cbase) = ov;
            }
        } else {
            #pragma unroll
            for (int jh = 0; jh < 2; jh++) {
                int cbase = col0 + ((jh == 0) ? (tx * 4) : (64 + tx * 4));
                int jb = jh * 4;
                float4 ov = { acc[i][jb + 0], acc[i][jb + 1], acc[i][jb + 2], acc[i][jb + 3] };
                *(float4*)(C + rowoff + cbase) = ov;
            }
        }
    }
}

// ---------------- fp32 flash attention (causal) ----------------
// block = one (b, h, q-tile of 64 rows); 256 threads; 4x4 register sub-tiles.
#define PADW 68
#define ATT_SMEM (4 * 64 * PADW * (int)sizeof(float))  // 69632 B

__global__ void __launch_bounds__(256) attn_kernel()
{
    extern __shared__ float sm[];
    float (*Qs)[PADW] = (float(*)[PADW])(sm);
    float (*Ks)[PADW] = (float(*)[PADW])(sm + 1 * 64 * PADW);
    float (*Vs)[PADW] = (float(*)[PADW])(sm + 2 * 64 * PADW);
    float (*Ps)[PADW] = (float(*)[PADW])(sm + 3 * 64 * PADW);

    const int tid = threadIdx.x;
    const int qt  = blockIdx.x;       // 0..31
    const int bh  = blockIdx.y;       // 0..63
    const int b   = bh >> 4;
    const int h   = bh & 15;

    const float* Qb = g_Q + (size_t)b * SEQ * DIM + h * DH;
    const float* Kb = g_K + (size_t)b * SEQ * DIM + h * DH;
    const float* Vb = g_V + (size_t)b * SEQ * DIM + h * DH;

    const int lr = tid >> 4;           // 0..15
    const int lc = (tid & 15) * 4;     // 0..60

    #pragma unroll
    for (int it = 0; it < 4; it++) {
        int r = lr + it * 16;
        *(float4*)&Qs[r][lc] = *(const float4*)(Qb + (size_t)(qt * 64 + r) * DIM + lc);
    }

    const int qr = (tid >> 4) * 4;     // q-row group
    const int kc = (tid & 15) * 4;     // k-col / dh-col group

    float m[4], l[4], o[4][4];
    #pragma unroll
    for (int i = 0; i < 4; i++) {
        m[i] = -INFINITY;
        l[i] = 0.0f;
        #pragma unroll
        for (int j = 0; j < 4; j++) o[i][j] = 0.0f;
    }
    __syncthreads();

    for (int kvt = 0; kvt <= qt; kvt++) {
        #pragma unroll
        for (int it = 0; it < 4; it++) {
            int r = lr + it * 16;
            *(float4*)&Ks[r][lc] = *(const float4*)(Kb + (size_t)(kvt * 64 + r) * DIM + lc);
            *(float4*)&Vs[r][lc] = *(const float4*)(Vb + (size_t)(kvt * 64 + r) * DIM + lc);
        }
        __syncthreads();

        // S = Q @ K^T (4x4 per thread)
        float sc[4][4];
        #pragma unroll
        for (int i = 0; i < 4; i++)
            #pragma unroll
            for (int j = 0; j < 4; j++)
                sc[i][j] = 0.0f;

        #pragma unroll
        for (int kk = 0; kk < DH; kk += 4) {
            float4 qv[4], kv[4];
            #pragma unroll
            for (int i = 0; i < 4; i++) qv[i] = *(const float4*)&Qs[qr + i][kk];
            #pragma unroll
            for (int j = 0; j < 4; j++) kv[j] = *(const float4*)&Ks[kc + j][kk];
            #pragma unroll
            for (int i = 0; i < 4; i++)
                #pragma unroll
                for (int j = 0; j < 4; j++)
                    sc[i][j] += qv[i].x * kv[j].x + qv[i].y * kv[j].y
                              + qv[i].z * kv[j].z + qv[i].w * kv[j].w;
        }

        const bool diag = (kvt == qt);
        #pragma unroll
        for (int i = 0; i < 4; i++) {
            float rowmax = -INFINITY;
            #pragma unroll
            for (int j = 0; j < 4; j++) {
                float v = sc[i][j] * 0.125f;
                if (diag && (kc + j) > (qr + i)) v = -INFINITY;
                sc[i][j] = v;
                rowmax = fmaxf(rowmax, v);
            }
            rowmax = fmaxf(rowmax, __shfl_xor_sync(0xffffffffu, rowmax, 8));
            rowmax = fmaxf(rowmax, __shfl_xor_sync(0xffffffffu, rowmax, 4));
            rowmax = fmaxf(rowmax, __shfl_xor_sync(0xffffffffu, rowmax, 2));
            rowmax = fmaxf(rowmax, __shfl_xor_sync(0xffffffffu, rowmax, 1));
            float mn = fmaxf(m[i], rowmax);
            float al = __expf(m[i] - mn);
            m[i] = mn;
            l[i] *= al;
            #pragma unroll
            for (int j = 0; j < 4; j++) o[i][j] *= al;
            float rs = 0.0f;
            #pragma unroll
            for (int j = 0; j < 4; j++) {
                float p = __expf(sc[i][j] - mn);
                sc[i][j] = p;
                rs += p;
            }
            rs += __shfl_xor_sync(0xffffffffu, rs, 8);
            rs += __shfl_xor_sync(0xffffffffu, rs, 4);
            rs += __shfl_xor_sync(0xffffffffu, rs, 2);
            rs += __shfl_xor_sync(0xffffffffu, rs, 1);
            l[i] += rs;
            float4 pv = { sc[i][0], sc[i][1], sc[i][2], sc[i][3] };
            *(float4*)&Ps[qr + i][kc] = pv;
        }
        __syncthreads();

        // O += P @ V
        #pragma unroll
        for (int kk = 0; kk < DH; kk += 4) {
            float4 pr[4], vv[4];
            #pragma unroll
            for (int i = 0; i < 4; i++) pr[i] = *(const float4*)&Ps[qr + i][kk];
            #pragma unroll
            for (int t = 0; t < 4; t++) vv[t] = *(const float4*)&Vs[kk + t][kc];
            #pragma unroll
            for (int i = 0; i < 4; i++) {
                o[i][0] += pr[i].x * vv[0].x + pr[i].y * vv[1].x + pr[i].z * vv[2].x + pr[i].w * vv[3].x;
                o[i][1] += pr[i].x * vv[0].y + pr[i].y * vv[1].y + pr[i].z * vv[2].y + pr[i].w * vv[3].y;
                o[i][2] += pr[i].x * vv[0].z + pr[i].y * vv[1].z + pr[i].z * vv[2].z + pr[i].w * vv[3].z;
                o[i][3] += pr[i].x * vv[0].w + pr[i].y * vv[1].w + pr[i].z * vv[2].w + pr[i].w * vv[3].w;
            }
        }
        __syncthreads();
    }

    float* Ob = g_O + (size_t)b * SEQ * DIM + h * DH;
    #pragma unroll
    for (int i = 0; i < 4; i++) {
        float inv = 1.0f / l[i];
        float4 ov = { o[i][0] * inv, o[i][1] * inv, o[i][2] * inv, o[i][3] * inv };
        *(float4*)(Ob + (size_t)(qt * 64 + qr + i) * DIM + kc) = ov;
    }
}

// ---------------- launch ----------------
extern "C" void kernel_launch(void* const* d_in, const int* in_sizes, int n_in,
                              void* d_out, int out_size)
{
    const float* x  = (const float*)d_in[0];
    const float* WQ = (const float*)d_in[1];
    const float* WK = (const float*)d_in[2];
    const float* WV = (const float*)d_in[3];
    const float* WO = (const float*)d_in[4];
    const int*  pos = (const int*)d_in[5];
    float* out = (float*)d_out;

    cudaFuncSetAttribute(attn_kernel, cudaFuncAttributeMaxDynamicSharedMemorySize, ATT_SMEM);

    rope_table_kernel<<<(SEQ * 32 + 255) / 256, 256>>>(pos);

    dim3 ggrid(DIM / BN, NROWS / BM);   // (8, 64)
    gemm_kernel<0><<<ggrid, 256>>>(x, WQ, nullptr);
    gemm_kernel<1><<<ggrid, 256>>>(x, WK, nullptr);
    gemm_kernel<2><<<ggrid, 256>>>(x, WV, nullptr);

    attn_kernel<<<dim3(SEQ / 64, BATCH * NHEAD), 256, ATT_SMEM>>>();

    gemm_kernel<3><<<ggrid, 256>>>(nullptr, WO, out);
}

// round 3
// speedup vs baseline: 1.5498x; 1.5498x over previous
#include <cuda_runtime.h>
#include <math.h>
#include <stdint.h>

#define BATCH 4
#define SEQ   2048
#define DIM   1024
#define NHEAD 16
#define DH    64
#define NROWS (BATCH*SEQ)   // 8192

// ---------------- scratch (device globals: allocation-free rule) ----------------
__device__ float g_Q[(size_t)NROWS * DIM];
__device__ float g_K[(size_t)NROWS * DIM];
__device__ float g_V[(size_t)NROWS * DIM];
__device__ float g_O[(size_t)NROWS * DIM];
__device__ float g_cos[SEQ * 32];
__device__ float g_sin[SEQ * 32];

// ---------------- helpers ----------------
__device__ __forceinline__ unsigned f2tf32(float x) {
    unsigned r;
    asm("cvt.rna.tf32.f32 %0, %1;" : "=r"(r) : "f"(x));
    return r;
}
__device__ __forceinline__ void split_tf32(float x, unsigned& hi, unsigned& lo) {
    hi = f2tf32(x);
    float r = x - __uint_as_float(hi);
    lo = f2tf32(r);
}
__device__ __forceinline__ void mma8(float* c, const unsigned* a, const unsigned* b) {
    asm volatile(
        "mma.sync.aligned.m16n8k8.row.col.f32.tf32.tf32.f32 "
        "{%0,%1,%2,%3},{%4,%5,%6,%7},{%8,%9},{%0,%1,%2,%3};"
        : "+f"(c[0]), "+f"(c[1]), "+f"(c[2]), "+f"(c[3])
        : "r"(a[0]), "r"(a[1]), "r"(a[2]), "r"(a[3]), "r"(b[0]), "r"(b[1]));
}
__device__ __forceinline__ void cp16(float* smem_dst, const float* gmem_src) {
    unsigned s = (unsigned)__cvta_generic_to_shared(smem_dst);
    asm volatile("cp.async.ca.shared.global [%0], [%1], 16;" :: "r"(s), "l"(gmem_src));
}
__device__ __forceinline__ void cp_commit() {
    asm volatile("cp.async.commit_group;");
}
template<int N>
__device__ __forceinline__ void cp_wait() {
    asm volatile("cp.async.wait_group %0;" :: "n"(N));
}

// ---------------- RoPE table ----------------
__global__ void rope_table_kernel(const int* __restrict__ pos)
{
    int idx = blockIdx.x * blockDim.x + threadIdx.x;
    if (idx >= SEQ * 32) return;
    int s = idx >> 5;
    int p = idx & 31;
    float inv = powf(10000.0f, -(float)(2 * p) / (float)DH);
    float ang = (float)pos[s] * inv;
    float sv, cv;
    sincosf(ang, &sv, &cv);
    g_cos[idx] = cv;
    g_sin[idx] = sv;
}

// ---------------- tf32x3 tensor-core GEMM ----------------
// C[i,j] = sum_d X[i,d] * W[j,d]   (A row-major, B K-major -> mma row.col)
// MODE: 0 -> C=g_Q (RoPE), 1 -> C=g_K (RoPE), 2 -> C=g_V, 3 -> X=g_O, C=Cout
#define GBM 128
#define GBN 128
#define GBK 32
#define GPAD 36
#define GXS(st) ((st) * (GBM * GPAD))
#define GWS(st) (2 * (GBM * GPAD) + (st) * (GBN * GPAD))
#define GEMM_SMEM (4 * GBM * GPAD * (int)sizeof(float))   // 73728

template<int MODE>
__global__ void __launch_bounds__(256) gemm_tc(const float* __restrict__ Xin,
                                               const float* __restrict__ W,
                                               float* __restrict__ Cout)
{
    extern __shared__ float sm[];
    const float* X = (MODE == 3) ? g_O : Xin;
    float* C = (MODE == 0) ? g_Q : (MODE == 1) ? g_K : (MODE == 2) ? g_V : Cout;

    const int tid  = threadIdx.x;
    const int lane = tid & 31;
    const int wid  = tid >> 5;
    const int g    = lane >> 2;   // 0..7
    const int t    = lane & 3;    // 0..3
    const int wm   = wid & 1;     // m half (64 rows)
    const int wn   = wid >> 1;    // n quarter (32 cols)

    const int row0 = blockIdx.y * GBM;
    const int col0 = blockIdx.x * GBN;

    // per-thread gmem load coords: 4 float4 for X, 4 for W per stage
    const int lr = (tid >> 3);        // used with +128 offset
    const int lcol = (tid & 7) * 4;

    float acc[4][4][4];
    #pragma unroll
    for (int im = 0; im < 4; im++)
        #pragma unroll
        for (int in = 0; in < 4; in++)
            #pragma unroll
            for (int e = 0; e < 4; e++)
                acc[im][in][e] = 0.0f;

    // stage loader
    auto load_stage = [&](int st, int kt) {
        int k0 = kt * GBK;
        #pragma unroll
        for (int i = 0; i < 4; i++) {
            int r = lr + i * 32;   // 256 threads/8 = 32 rows per step, 4 steps = 128
            cp16(&sm[GXS(st) + r * GPAD + lcol],
                 X + (size_t)(row0 + r) * DIM + k0 + lcol);
        }
        #pragma unroll
        for (int i = 0; i < 4; i++) {
            int r = lr + i * 32;
            cp16(&sm[GWS(st) + r * GPAD + lcol],
                 W + (size_t)(col0 + r) * DIM + k0 + lcol);
        }
    };

    load_stage(0, 0);
    cp_commit();

    const int NKT = DIM / GBK;  // 32
    for (int kt = 0; kt < NKT; kt++) {
        int st = kt & 1;
        if (kt + 1 < NKT) {
            load_stage(st ^ 1, kt + 1);
            cp_commit();
            cp_wait<1>();
        } else {
            cp_wait<0>();
        }
        __syncthreads();

        const float* xs = sm + GXS(st);
        const float* ws = sm + GWS(st);

        #pragma unroll
        for (int kq = 0; kq < GBK / 8; kq++) {
            int kk = kq * 8;
            unsigned ahi[4][4], alo[4][4];
            #pragma unroll
            for (int im = 0; im < 4; im++) {
                int rb = wm * 64 + im * 16;
                float x0 = xs[(rb + g) * GPAD + kk + t];
                float x1 = xs[(rb + 8 + g) * GPAD + kk + t];
                float x2 = xs[(rb + g) * GPAD + kk + t + 4];
                float x3 = xs[(rb + 8 + g) * GPAD + kk + t + 4];
                split_tf32(x0, ahi[im][0], alo[im][0]);
                split_tf32(x1, ahi[im][1], alo[im][1]);
                split_tf32(x2, ahi[im][2], alo[im][2]);
                split_tf32(x3, ahi[im][3], alo[im][3]);
            }
            unsigned bhi[4][2], blo[4][2];
            #pragma unroll
            for (int in = 0; in < 4; in++) {
                int nb = wn * 32 + in * 8 + g;
                float b0 = ws[nb * GPAD + kk + t];
                float b1 = ws[nb * GPAD + kk + t + 4];
                split_tf32(b0, bhi[in][0], blo[in][0]);
                split_tf32(b1, bhi[in][1], blo[in][1]);
            }
            #pragma unroll
            for (int im = 0; im < 4; im++)
                #pragma unroll
                for (int in = 0; in < 4; in++) {
                    mma8(acc[im][in], ahi[im], bhi[in]);
                    mma8(acc[im][in], ahi[im], blo[in]);
                    mma8(acc[im][in], alo[im], bhi[in]);
                }
        }
        __syncthreads();
    }

    // epilogue
    #pragma unroll
    for (int im = 0; im < 4; im++) {
        int r0 = row0 + wm * 64 + im * 16 + g;
        int r1 = r0 + 8;
        #pragma unroll
        for (int in = 0; in < 4; in++) {
            int c = col0 + wn * 32 + in * 8 + 2 * t;
            float v0 = acc[im][in][0], v1 = acc[im][in][1];
            float v2 = acc[im][in][2], v3 = acc[im][in][3];
            if (MODE <= 1) {
                int p = (c & 63) >> 1;
                int s0 = r0 & (SEQ - 1);
                int s1 = r1 & (SEQ - 1);
                float cv0 = g_cos[s0 * 32 + p], sv0 = g_sin[s0 * 32 + p];
                float cv1 = g_cos[s1 * 32 + p], sv1 = g_sin[s1 * 32 + p];
                float2 o0 = { v0 * cv0 - v1 * sv0, v0 * sv0 + v1 * cv0 };
                float2 o1 = { v2 * cv1 - v3 * sv1, v2 * sv1 + v3 * cv1 };
                *(float2*)(C + (size_t)r0 * DIM + c) = o0;
                *(float2*)(C + (size_t)r1 * DIM + c) = o1;
            } else {
                float2 o0 = { v0, v1 };
                float2 o1 = { v2, v3 };
                *(float2*)(C + (size_t)r0 * DIM + c) = o0;
                *(float2*)(C + (size_t)r1 * DIM + c) = o1;
            }
        }
    }
}

// ---------------- flash attention with tf32x3 mma ----------------
// CTA: 128 q-rows x 64 kv tile; 4 warps, each warp 32 q-rows.
#define QPAD 68
#define KPAD 68
#define VPAD 72
#define PPAD 68
#define AQS 0                                // Qs[128][68]
#define AKS (128 * QPAD)                     // Ks[64][68]
#define AVS (AKS + 64 * KPAD)                // Vs[64][72]
#define APS (AVS + 64 * VPAD)                // Ps[128][68]
#define ATT_SMEM ((APS + 128 * PPAD) * (int)sizeof(float))   // 105472

__global__ void __launch_bounds__(128, 1) attn_tc_kernel()
{
    extern __shared__ float sm[];
    float* qs = sm + AQS;
    float* ks = sm + AKS;
    float* vs = sm + AVS;
    float* ps = sm + APS;

    const int tid  = threadIdx.x;
    const int lane = tid & 31;
    const int wid  = tid >> 5;   // 0..3
    const int g    = lane >> 2;
    const int t    = lane & 3;

    const int qt = blockIdx.x;          // 0..15 (q-tiles of 128)
    const int q0 = qt * 128;
    const int bh = blockIdx.y;          // 0..63
    const int b  = bh >> 4;
    const int h  = bh & 15;

    const float* Qb = g_Q + (size_t)b * SEQ * DIM + h * DH;
    const float* Kb = g_K + (size_t)b * SEQ * DIM + h * DH;
    const float* Vb = g_V + (size_t)b * SEQ * DIM + h * DH;

    // load Q tile (128 x 64) once
    #pragma unroll
    for (int i = 0; i < 16; i++) {
        int idx = tid + i * 128;
        int r = idx >> 4;
        int c = (idx & 15) * 4;
        *(float4*)&qs[r * QPAD + c] = *(const float4*)(Qb + (size_t)(q0 + r) * DIM + c);
    }

    float o[2][8][4];
    float m[4], l[4];
    #pragma unroll
    for (int im = 0; im < 2; im++)
        #pragma unroll
        for (int n = 0; n < 8; n++)
            #pragma unroll
            for (int e = 0; e < 4; e++)
                o[im][n][e] = 0.0f;
    #pragma unroll
    for (int i = 0; i < 4; i++) { m[i] = -INFINITY; l[i] = 0.0f; }

    __syncthreads();

    const int wq0 = q0 + wid * 32;   // warp's first q row
    const int ntiles = 2 * qt + 2;

    for (int kvt = 0; kvt < ntiles; kvt++) {
        int kv0 = kvt * 64;
        // stage K (64x64) and V (64x64)
        #pragma unroll
        for (int i = 0; i < 8; i++) {
            int idx = tid + i * 128;
            int r = idx >> 4;
            int c = (idx & 15) * 4;
            *(float4*)&ks[r * KPAD + c] = *(const float4*)(Kb + (size_t)(kv0 + r) * DIM + c);
            *(float4*)&vs[r * VPAD + c] = *(const float4*)(Vb + (size_t)(kv0 + r) * DIM + c);
        }
        __syncthreads();

        const bool active = (kv0 <= wq0 + 31);
        if (active) {
            // ---- S = Q K^T ----
            float s[2][8][4];
            #pragma unroll
            for (int im = 0; im < 2; im++)
                #pragma unroll
                for (int n = 0; n < 8; n++)
                    #pragma unroll
                    for (int e = 0; e < 4; e++)
                        s[im][n][e] = 0.0f;

            #pragma unroll
            for (int kd = 0; kd < 8; kd++) {
                int kk = kd * 8;
                unsigned ahi[2][4], alo[2][4];
                #pragma unroll
                for (int im = 0; im < 2; im++) {
                    int rb = wid * 32 + im * 16;
                    split_tf32(qs[(rb + g) * QPAD + kk + t],         ahi[im][0], alo[im][0]);
                    split_tf32(qs[(rb + 8 + g) * QPAD + kk + t],     ahi[im][1], alo[im][1]);
                    split_tf32(qs[(rb + g) * QPAD + kk + t + 4],     ahi[im][2], alo[im][2]);
                    split_tf32(qs[(rb + 8 + g) * QPAD + kk + t + 4], ahi[im][3], alo[im][3]);
                }
                unsigned bhi[8][2], blo[8][2];
                #pragma unroll
                for (int n = 0; n < 8; n++) {
                    split_tf32(ks[(n * 8 + g) * KPAD + kk + t],     bhi[n][0], blo[n][0]);
                    split_tf32(ks[(n * 8 + g) * KPAD + kk + t + 4], bhi[n][1], blo[n][1]);
                }
                #pragma unroll
                for (int im = 0; im < 2; im++)
                    #pragma unroll
                    for (int n = 0; n < 8; n++) {
                        mma8(s[im][n], ahi[im], bhi[n]);
                        mma8(s[im][n], ahi[im], blo[n]);
                        mma8(s[im][n], alo[im], bhi[n]);
                    }
            }

            // ---- scale + causal mask ----
            const bool needmask = (kv0 + 63) > wq0;
            #pragma unroll
            for (int im = 0; im < 2; im++)
                #pragma unroll
                for (int n = 0; n < 8; n++)
                    #pragma unroll
                    for (int e = 0; e < 4; e++) {
                        float v = s[im][n][e] * 0.125f;
                        if (needmask) {
                            int col = kv0 + n * 8 + 2 * t + (e & 1);
                            int row = wq0 + im * 16 + g + ((e >> 1) * 8);
                            if (col > row) v = -1e30f;
                        }
                        s[im][n][e] = v;
                    }

            // ---- streaming softmax (rows: im*2 + half) ----
            #pragma unroll
            for (int im = 0; im < 2; im++) {
                #pragma unroll
                for (int hh = 0; hh < 2; hh++) {
                    int ri = im * 2 + hh;
                    float rowmax = -INFINITY;
                    #pragma unroll
                    for (int n = 0; n < 8; n++) {
                        rowmax = fmaxf(rowmax, s[im][n][hh * 2 + 0]);
                        rowmax = fmaxf(rowmax, s[im][n][hh * 2 + 1]);
                    }
                    rowmax = fmaxf(rowmax, __shfl_xor_sync(0xffffffffu, rowmax, 1));
                    rowmax = fmaxf(rowmax, __shfl_xor_sync(0xffffffffu, rowmax, 2));
                    float mnew = fmaxf(m[ri], rowmax);
                    float alpha = __expf(m[ri] - mnew);
                    m[ri] = mnew;
                    float rs = 0.0f;
                    #pragma unroll
                    for (int n = 0; n < 8; n++) {
                        float p0 = __expf(s[im][n][hh * 2 + 0] - mnew);
                        float p1 = __expf(s[im][n][hh * 2 + 1] - mnew);
                        s[im][n][hh * 2 + 0] = p0;
                        s[im][n][hh * 2 + 1] = p1;
                        rs += p0 + p1;
                    }
                    rs += __shfl_xor_sync(0xffffffffu, rs, 1);
                    rs += __shfl_xor_sync(0xffffffffu, rs, 2);
                    l[ri] = l[ri] * alpha + rs;
                    #pragma unroll
                    for (int n = 0; n < 8; n++) {
                        o[im][n][hh * 2 + 0] *= alpha;
                        o[im][n][hh * 2 + 1] *= alpha;
                    }
                }
            }

            // ---- store P to warp-private smem ----
            #pragma unroll
            for (int im = 0; im < 2; im++) {
                int rb = wid * 32 + im * 16;
                #pragma unroll
                for (int n = 0; n < 8; n++) {
                    float2 p0 = { s[im][n][0], s[im][n][1] };
                    float2 p1 = { s[im][n][2], s[im][n][3] };
                    *(float2*)&ps[(rb + g) * PPAD + n * 8 + 2 * t] = p0;
                    *(float2*)&ps[(rb + 8 + g) * PPAD + n * 8 + 2 * t] = p1;
                }
            }
            __syncwarp();

            // ---- O += P V ----
            #pragma unroll
            for (int kd = 0; kd < 8; kd++) {
                int kk = kd * 8;
                unsigned ahi[2][4], alo[2][4];
                #pragma unroll
                for (int im = 0; im < 2; im++) {
                    int rb = wid * 32 + im * 16;
                    split_tf32(ps[(rb + g) * PPAD + kk + t],         ahi[im][0], alo[im][0]);
                    split_tf32(ps[(rb + 8 + g) * PPAD + kk + t],     ahi[im][1], alo[im][1]);
                    split_tf32(ps[(rb + g) * PPAD + kk + t + 4],     ahi[im][2], alo[im][2]);
                    split_tf32(ps[(rb + 8 + g) * PPAD + kk + t + 4], ahi[im][3], alo[im][3]);
                }
                unsigned bhi[8][2], blo[8][2];
                #pragma unroll
                for (int n = 0; n < 8; n++) {
                    split_tf32(vs[(kk + t) * VPAD + n * 8 + g],     bhi[n][0], blo[n][0]);
                    split_tf32(vs[(kk + t + 4) * VPAD + n * 8 + g], bhi[n][1], blo[n][1]);
                }
                #pragma unroll
                for (int im = 0; im < 2; im++)
                    #pragma unroll
                    for (int n = 0; n < 8; n++) {
                        mma8(o[im][n], ahi[im], bhi[n]);
                        mma8(o[im][n], ahi[im], blo[n]);
                        mma8(o[im][n], alo[im], bhi[n]);
                    }
            }
        }
        __syncthreads();
    }

    // ---- epilogue: normalize + write ----
    float* Ob = g_O + (size_t)b * SEQ * DIM + h * DH;
    #pragma unroll
    for (int im = 0; im < 2; im++) {
        int r0 = q0 + wid * 32 + im * 16 + g;
        int r1 = r0 + 8;
        float inv0 = 1.0f / l[im * 2 + 0];
        float inv1 = 1.0f / l[im * 2 + 1];
        #pragma unroll
        for (int n = 0; n < 8; n++) {
            int c = n * 8 + 2 * t;
            float2 o0 = { o[im][n][0] * inv0, o[im][n][1] * inv0 };
            float2 o1 = { o[im][n][2] * inv1, o[im][n][3] * inv1 };
            *(float2*)(Ob + (size_t)r0 * DIM + c) = o0;
            *(float2*)(Ob + (size_t)r1 * DIM + c) = o1;
        }
    }
}

// ---------------- launch ----------------
extern "C" void kernel_launch(void* const* d_in, const int* in_sizes, int n_in,
                              void* d_out, int out_size)
{
    const float* x  = (const float*)d_in[0];
    const float* WQ = (const float*)d_in[1];
    const float* WK = (const float*)d_in[2];
    const float* WV = (const float*)d_in[3];
    const float* WO = (const float*)d_in[4];
    const int*  pos = (const int*)d_in[5];
    float* out = (float*)d_out;

    cudaFuncSetAttribute(gemm_tc<0>, cudaFuncAttributeMaxDynamicSharedMemorySize, GEMM_SMEM);
    cudaFuncSetAttribute(gemm_tc<1>, cudaFuncAttributeMaxDynamicSharedMemorySize, GEMM_SMEM);
    cudaFuncSetAttribute(gemm_tc<2>, cudaFuncAttributeMaxDynamicSharedMemorySize, GEMM_SMEM);
    cudaFuncSetAttribute(gemm_tc<3>, cudaFuncAttributeMaxDynamicSharedMemorySize, GEMM_SMEM);
    cudaFuncSetAttribute(attn_tc_kernel, cudaFuncAttributeMaxDynamicSharedMemorySize, ATT_SMEM);

    rope_table_kernel<<<(SEQ * 32 + 255) / 256, 256>>>(pos);

    dim3 ggrid(DIM / GBN, NROWS / GBM);   // (8, 64)
    gemm_tc<0><<<ggrid, 256, GEMM_SMEM>>>(x, WQ, nullptr);
    gemm_tc<1><<<ggrid, 256, GEMM_SMEM>>>(x, WK, nullptr);
    gemm_tc<2><<<ggrid, 256, GEMM_SMEM>>>(x, WV, nullptr);

    attn_tc_kernel<<<dim3(SEQ / 128, BATCH * NHEAD), 128, ATT_SMEM>>>();

    gemm_tc<3><<<ggrid, 256, GEMM_SMEM>>>(nullptr, WO, out);
}

// round 5
// speedup vs baseline: 2.8016x; 1.8076x over previous
#include <cuda_runtime.h>
#include <cuda_fp16.h>
#include <math.h>
#include <stdint.h>

#define BATCH 4
#define SEQ   2048
#define DIM   1024
#define NHEAD 16
#define DH    64
#define NROWS (BATCH*SEQ)   // 8192

// ---------------- scratch (device globals: allocation-free rule) ----------------
__device__ float g_Q[(size_t)NROWS * DIM];
__device__ float g_K[(size_t)NROWS * DIM];
__device__ float g_V[(size_t)NROWS * DIM];
__device__ float g_O[(size_t)NROWS * DIM];
__device__ float g_cos[SEQ * 32];
__device__ float g_sin[SEQ * 32];

// ---------------- helpers ----------------
__device__ __forceinline__ void splitf(float x, __half& h, __half& l) {
    h = __float2half_rn(x);
    l = __float2half_rn(x - __half2float(h));
}
// m16n8k16 fp16 mma, fp32 accum
__device__ __forceinline__ void mma16(float* c, const uint32_t* a, const uint32_t* b) {
    asm volatile(
        "mma.sync.aligned.m16n8k16.row.col.f32.f16.f16.f32 "
        "{%0,%1,%2,%3},{%4,%5,%6,%7},{%8,%9},{%0,%1,%2,%3};"
        : "+f"(c[0]), "+f"(c[1]), "+f"(c[2]), "+f"(c[3])
        : "r"(a[0]), "r"(a[1]), "r"(a[2]), "r"(a[3]), "r"(b[0]), "r"(b[1]));
}
__device__ __forceinline__ void ldmx4t(uint32_t& d0, uint32_t& d1, uint32_t& d2, uint32_t& d3,
                                       uint32_t saddr) {
    asm volatile("ldmatrix.sync.aligned.m8n8.x4.trans.shared.b16 {%0,%1,%2,%3}, [%4];"
                 : "=r"(d0), "=r"(d1), "=r"(d2), "=r"(d3) : "r"(saddr));
}

// ---------------- RoPE table ----------------
__global__ void rope_table_kernel(const int* __restrict__ pos)
{
    int idx = blockIdx.x * blockDim.x + threadIdx.x;
    if (idx >= SEQ * 32) return;
    int s = idx >> 5;
    int p = idx & 31;
    float inv = powf(10000.0f, -(float)(2 * p) / (float)DH);
    float ang = (float)pos[s] * inv;
    float sv, cv;
    sincosf(ang, &sv, &cv);
    g_cos[idx] = cv;
    g_sin[idx] = sv;
}

// ---------------- fp16x2 tensor-core GEMM ----------------
// C[i,j] = sum_d X[i,d] * W[j,d]; CTA 128x128, chunk K=32.
// Planes: Ahi, Alo, Bhi, Blo half[128][40]. W prescaled x256, epilogue x(1/256).
// MODE: 0 -> C=g_Q (RoPE), 1 -> C=g_K (RoPE), 2 -> C=g_V, 3 -> X=g_O, C=Cout
#define GKP 40                 // halves per row
#define GPL (128 * GKP)        // 5120 halves per plane
#define GEMM_SMEM (4 * GPL * 2)  // 40960 B

template<int MODE>
__global__ void __launch_bounds__(256, 2) gemm_h2(const float* __restrict__ Xin,
                                                  const float* __restrict__ W,
                                                  float* __restrict__ Cout)
{
    extern __shared__ __half smh[];
    const float* X = (MODE == 3) ? g_O : Xin;
    float* C = (MODE == 0) ? g_Q : (MODE == 1) ? g_K : (MODE == 2) ? g_V : Cout;

    __half* Ah = smh;
    __half* Al = smh + GPL;
    __half* Bh = smh + 2 * GPL;
    __half* Bl = smh + 3 * GPL;

    const int tid  = threadIdx.x;
    const int lane = tid & 31;
    const int wid  = tid >> 5;
    const int g    = lane >> 2;
    const int t    = lane & 3;
    const int wm   = wid & 1;
    const int wn   = wid >> 1;

    const int row0 = blockIdx.y * 128;
    const int col0 = blockIdx.x * 128;

    float acc[4][4][4];
    #pragma unroll
    for (int im = 0; im < 4; im++)
        #pragma unroll
        for (int in = 0; in < 4; in++)
            #pragma unroll
            for (int e = 0; e < 4; e++)
                acc[im][in][e] = 0.0f;

    const int NKT = DIM / 32;   // 32 chunks
    for (int kt = 0; kt < NKT; kt++) {
        const int k0 = kt * 32;
        __syncthreads();
        // load + split chunk: 128x32 for A and B, 4 float4 each per thread
        #pragma unroll
        for (int i = 0; i < 4; i++) {
            int pos = tid + i * 256;
            int row = pos >> 3;
            int cq  = (pos & 7) * 4;
            float4 xv = *(const float4*)(X + (size_t)(row0 + row) * DIM + k0 + cq);
            __half h0, l0, h1, l1, h2, l2, h3, l3;
            splitf(xv.x, h0, l0); splitf(xv.y, h1, l1);
            splitf(xv.z, h2, l2); splitf(xv.w, h3, l3);
            *(__half2*)&Ah[row * GKP + cq]     = __halves2half2(h0, h1);
            *(__half2*)&Ah[row * GKP + cq + 2] = __halves2half2(h2, h3);
            *(__half2*)&Al[row * GKP + cq]     = __halves2half2(l0, l1);
            *(__half2*)&Al[row * GKP + cq + 2] = __halves2half2(l2, l3);
            float4 wv = *(const float4*)(W + (size_t)(col0 + row) * DIM + k0 + cq);
            wv.x *= 256.0f; wv.y *= 256.0f; wv.z *= 256.0f; wv.w *= 256.0f;
            splitf(wv.x, h0, l0); splitf(wv.y, h1, l1);
            splitf(wv.z, h2, l2); splitf(wv.w, h3, l3);
            *(__half2*)&Bh[row * GKP + cq]     = __halves2half2(h0, h1);
            *(__half2*)&Bh[row * GKP + cq + 2] = __halves2half2(h2, h3);
            *(__half2*)&Bl[row * GKP + cq]     = __halves2half2(l0, l1);
            *(__half2*)&Bl[row * GKP + cq + 2] = __halves2half2(l2, l3);
        }
        __syncthreads();

        #pragma unroll
        for (int kq = 0; kq < 2; kq++) {
            const int kk = kq * 16;
            // B fragments for all 4 n-blocks
            uint32_t bhi[4][2], blo[4][2];
            #pragma unroll
            for (int in = 0; in < 4; in++) {
                int col = wn * 32 + in * 8 + g;
                bhi[in][0] = *(const uint32_t*)&Bh[col * GKP + kk + 2 * t];
                bhi[in][1] = *(const uint32_t*)&Bh[col * GKP + kk + 8 + 2 * t];
                blo[in][0] = *(const uint32_t*)&Bl[col * GKP + kk + 2 * t];
                blo[in][1] = *(const uint32_t*)&Bl[col * GKP + kk + 8 + 2 * t];
            }
            #pragma unroll
            for (int im = 0; im < 4; im++) {
                int rb = wm * 64 + im * 16;
                uint32_t ahi[4], alo[4];
                ahi[0] = *(const uint32_t*)&Ah[(rb + g) * GKP + kk + 2 * t];
                ahi[1] = *(const uint32_t*)&Ah[(rb + 8 + g) * GKP + kk + 2 * t];
                ahi[2] = *(const uint32_t*)&Ah[(rb + g) * GKP + kk + 8 + 2 * t];
                ahi[3] = *(const uint32_t*)&Ah[(rb + 8 + g) * GKP + kk + 8 + 2 * t];
                alo[0] = *(const uint32_t*)&Al[(rb + g) * GKP + kk + 2 * t];
                alo[1] = *(const uint32_t*)&Al[(rb + 8 + g) * GKP + kk + 2 * t];
                alo[2] = *(const uint32_t*)&Al[(rb + g) * GKP + kk + 8 + 2 * t];
                alo[3] = *(const uint32_t*)&Al[(rb + 8 + g) * GKP + kk + 8 + 2 * t];
                #pragma unroll
                for (int in = 0; in < 4; in++) {
                    mma16(acc[im][in], ahi, bhi[in]);
                    mma16(acc[im][in], ahi, blo[in]);
                    mma16(acc[im][in], alo, bhi[in]);
                }
            }
        }
    }

    // epilogue (undo W x256)
    const float sc = 1.0f / 256.0f;
    #pragma unroll
    for (int im = 0; im < 4; im++) {
        int r0 = row0 + wm * 64 + im * 16 + g;
        int r1 = r0 + 8;
        #pragma unroll
        for (int in = 0; in < 4; in++) {
            int c = col0 + wn * 32 + in * 8 + 2 * t;
            float v0 = acc[im][in][0] * sc, v1 = acc[im][in][1] * sc;
            float v2 = acc[im][in][2] * sc, v3 = acc[im][in][3] * sc;
            if (MODE <= 1) {
                int p = (c & 63) >> 1;
                int s0 = r0 & (SEQ - 1);
                int s1 = r1 & (SEQ - 1);
                float cv0 = g_cos[s0 * 32 + p], sv0 = g_sin[s0 * 32 + p];
                float cv1 = g_cos[s1 * 32 + p], sv1 = g_sin[s1 * 32 + p];
                float2 o0 = { v0 * cv0 - v1 * sv0, v0 * sv0 + v1 * cv0 };
                float2 o1 = { v2 * cv1 - v3 * sv1, v2 * sv1 + v3 * cv1 };
                *(float2*)(C + (size_t)r0 * DIM + c) = o0;
                *(float2*)(C + (size_t)r1 * DIM + c) = o1;
            } else {
                float2 o0 = { v0, v1 };
                float2 o1 = { v2, v3 };
                *(float2*)(C + (size_t)r0 * DIM + c) = o0;
                *(float2*)(C + (size_t)r1 * DIM + c) = o1;
            }
        }
    }
}

// ---------------- flash attention, fp16x2 mma ----------------
// CTA: 128 q-rows, 4 warps x 32 rows; kv tile 64.
// Planes (halves, row stride 72): Qhi/Qlo[128], Khi/Klo[64], Vhi/Vlo[64] (natural,
// transposed at read via ldmatrix.trans), Phi/Plo[128] (P prescaled x256).
#define AKP 72
#define OQH 0
#define OQL (128 * AKP)            // 9216
#define OKH (2 * 128 * AKP)        // 18432
#define OKL (OKH + 64 * AKP)       // 23040
#define OVH (OKH + 2 * 64 * AKP)   // 27648
#define OVL (OVH + 64 * AKP)       // 32256
#define OPH (OVH + 2 * 64 * AKP)   // 36864
#define OPL (OPH + 128 * AKP)      // 46080
#define ATT_SMEM ((OPL + 128 * AKP) * 2)   // 110592 B

__global__ void __launch_bounds__(128) attn_h2_kernel()
{
    extern __shared__ __half smh[];
    __half* qh = smh + OQH;  __half* ql = smh + OQL;
    __half* kh = smh + OKH;  __half* kl = smh + OKL;
    __half* vh = smh + OVH;  __half* vl = smh + OVL;
    __half* ph = smh + OPH;  __half* pl = smh + OPL;
    const uint32_t sb = (uint32_t)__cvta_generic_to_shared(smh);

    const int tid  = threadIdx.x;
    const int lane = tid & 31;
    const int wid  = tid >> 5;
    const int g    = lane >> 2;
    const int t    = lane & 3;

    const int qt = blockIdx.x;
    const int q0 = qt * 128;
    const int bh = blockIdx.y;
    const int b  = bh >> 4;
    const int h  = bh & 15;

    const float* Qb = g_Q + (size_t)b * SEQ * DIM + h * DH;
    const float* Kb = g_K + (size_t)b * SEQ * DIM + h * DH;
    const float* Vb = g_V + (size_t)b * SEQ * DIM + h * DH;

    // load + split Q once (128 x 64)
    #pragma unroll
    for (int i = 0; i < 16; i++) {
        int pos = tid + i * 128;
        int row = pos >> 4;
        int cq  = (pos & 15) * 4;
        float4 xv = *(const float4*)(Qb + (size_t)(q0 + row) * DIM + cq);
        __half h0, l0, h1, l1, h2, l2, h3, l3;
        splitf(xv.x, h0, l0); splitf(xv.y, h1, l1);
        splitf(xv.z, h2, l2); splitf(xv.w, h3, l3);
        *(__half2*)&qh[row * AKP + cq]     = __halves2half2(h0, h1);
        *(__half2*)&qh[row * AKP + cq + 2] = __halves2half2(h2, h3);
        *(__half2*)&ql[row * AKP + cq]     = __halves2half2(l0, l1);
        *(__half2*)&ql[row * AKP + cq + 2] = __halves2half2(l2, l3);
    }

    float o[2][8][4];
    float m[4], l[4];
    #pragma unroll
    for (int im = 0; im < 2; im++)
        #pragma unroll
        for (int n = 0; n < 8; n++)
            #pragma unroll
            for (int e = 0; e < 4; e++)
                o[im][n][e] = 0.0f;
    #pragma unroll
    for (int i = 0; i < 4; i++) { m[i] = -INFINITY; l[i] = 0.0f; }

    __syncthreads();

    const int wq0 = q0 + wid * 32;
    const int ntiles = 2 * qt + 2;

    for (int kvt = 0; kvt < ntiles; kvt++) {
        const int kv0 = kvt * 64;
        // load + split K, V tiles (64 x 64 each)
        #pragma unroll
        for (int i = 0; i < 8; i++) {
            int pos = tid + i * 128;
            int row = pos >> 4;
            int cq  = (pos & 15) * 4;
            float4 kv = *(const float4*)(Kb + (size_t)(kv0 + row) * DIM + cq);
            __half h0, l0, h1, l1, h2, l2, h3, l3;
            splitf(kv.x, h0, l0); splitf(kv.y, h1, l1);
            splitf(kv.z, h2, l2); splitf(kv.w, h3, l3);
            *(__half2*)&kh[row * AKP + cq]     = __halves2half2(h0, h1);
            *(__half2*)&kh[row * AKP + cq + 2] = __halves2half2(h2, h3);
            *(__half2*)&kl[row * AKP + cq]     = __halves2half2(l0, l1);
            *(__half2*)&kl[row * AKP + cq + 2] = __halves2half2(l2, l3);
            float4 vv = *(const float4*)(Vb + (size_t)(kv0 + row) * DIM + cq);
            splitf(vv.x, h0, l0); splitf(vv.y, h1, l1);
            splitf(vv.z, h2, l2); splitf(vv.w, h3, l3);
            *(__half2*)&vh[row * AKP + cq]     = __halves2half2(h0, h1);
            *(__half2*)&vh[row * AKP + cq + 2] = __halves2half2(h2, h3);
            *(__half2*)&vl[row * AKP + cq]     = __halves2half2(l0, l1);
            *(__half2*)&vl[row * AKP + cq + 2] = __halves2half2(l2, l3);
        }
        __syncthreads();

        const bool active = (kv0 <= wq0 + 31);
        if (active) {
            // ---- S = Q K^T ----
            float s[2][8][4];
            #pragma unroll
            for (int im = 0; im < 2; im++)
                #pragma unroll
                for (int n = 0; n < 8; n++)
                    #pragma unroll
                    for (int e = 0; e < 4; e++)
                        s[im][n][e] = 0.0f;

            #pragma unroll
            for (int ks = 0; ks < 4; ks++) {
                const int kk = ks * 16;
                uint32_t ahi[2][4], alo[2][4];
                #pragma unroll
                for (int im = 0; im < 2; im++) {
                    int rb = wid * 32 + im * 16;
                    ahi[im][0] = *(const uint32_t*)&qh[(rb + g) * AKP + kk + 2 * t];
                    ahi[im][1] = *(const uint32_t*)&qh[(rb + 8 + g) * AKP + kk + 2 * t];
                    ahi[im][2] = *(const uint32_t*)&qh[(rb + g) * AKP + kk + 8 + 2 * t];
                    ahi[im][3] = *(const uint32_t*)&qh[(rb + 8 + g) * AKP + kk + 8 + 2 * t];
                    alo[im][0] = *(const uint32_t*)&ql[(rb + g) * AKP + kk + 2 * t];
                    alo[im][1] = *(const uint32_t*)&ql[(rb + 8 + g) * AKP + kk + 2 * t];
                    alo[im][2] = *(const uint32_t*)&ql[(rb + g) * AKP + kk + 8 + 2 * t];
                    alo[im][3] = *(const uint32_t*)&ql[(rb + 8 + g) * AKP + kk + 8 + 2 * t];
                }
                #pragma unroll
                for (int n = 0; n < 8; n++) {
                    int col = n * 8 + g;
                    uint32_t bhi[2], blo[2];
                    bhi[0] = *(const uint32_t*)&kh[col * AKP + kk + 2 * t];
                    bhi[1] = *(const uint32_t*)&kh[col * AKP + kk + 8 + 2 * t];
                    blo[0] = *(const uint32_t*)&kl[col * AKP + kk + 2 * t];
                    blo[1] = *(const uint32_t*)&kl[col * AKP + kk + 8 + 2 * t];
                    #pragma unroll
                    for (int im = 0; im < 2; im++) {
                        mma16(s[im][n], ahi[im], bhi);
                        mma16(s[im][n], ahi[im], blo);
                        mma16(s[im][n], alo[im], bhi);
                    }
                }
            }

            // ---- scale + causal mask ----
            const bool needmask = (kv0 + 63) > wq0;
            #pragma unroll
            for (int im = 0; im < 2; im++)
                #pragma unroll
                for (int n = 0; n < 8; n++)
                    #pragma unroll
                    for (int e = 0; e < 4; e++) {
                        float v = s[im][n][e] * 0.125f;
                        if (needmask) {
                            int col = kv0 + n * 8 + 2 * t + (e & 1);
                            int row = wq0 + im * 16 + g + ((e >> 1) * 8);
                            if (col > row) v = -1e30f;
                        }
                        s[im][n][e] = v;
                    }

            // ---- streaming softmax ----
            #pragma unroll
            for (int im = 0; im < 2; im++) {
                #pragma unroll
                for (int hh = 0; hh < 2; hh++) {
                    int ri = im * 2 + hh;
                    float rowmax = -INFINITY;
                    #pragma unroll
                    for (int n = 0; n < 8; n++) {
                        rowmax = fmaxf(rowmax, s[im][n][hh * 2 + 0]);
                        rowmax = fmaxf(rowmax, s[im][n][hh * 2 + 1]);
                    }
                    rowmax = fmaxf(rowmax, __shfl_xor_sync(0xffffffffu, rowmax, 1));
                    rowmax = fmaxf(rowmax, __shfl_xor_sync(0xffffffffu, rowmax, 2));
                    float mnew = fmaxf(m[ri], rowmax);
                    float alpha = __expf(m[ri] - mnew);
                    m[ri] = mnew;
                    float rs = 0.0f;
                    #pragma unroll
                    for (int n = 0; n < 8; n++) {
                        float p0 = __expf(s[im][n][hh * 2 + 0] - mnew);
                        float p1 = __expf(s[im][n][hh * 2 + 1] - mnew);
                        s[im][n][hh * 2 + 0] = p0;
                        s[im][n][hh * 2 + 1] = p1;
                        rs += p0 + p1;
                    }
                    rs += __shfl_xor_sync(0xffffffffu, rs, 1);
                    rs += __shfl_xor_sync(0xffffffffu, rs, 2);
                    l[ri] = l[ri] * alpha + rs;
                    #pragma unroll
                    for (int n = 0; n < 8; n++) {
                        o[im][n][hh * 2 + 0] *= alpha;
                        o[im][n][hh * 2 + 1] *= alpha;
                    }
                }
            }

            // ---- split P (x256) into warp-private hi/lo planes ----
            #pragma unroll
            for (int im = 0; im < 2; im++) {
                int rb = wid * 32 + im * 16;
                #pragma unroll
                for (int n = 0; n < 8; n++) {
                    __half h0, l0, h1, l1;
                    splitf(s[im][n][0] * 256.0f, h0, l0);
                    splitf(s[im][n][1] * 256.0f, h1, l1);
                    *(__half2*)&ph[(rb + g) * AKP + n * 8 + 2 * t] = __halves2half2(h0, h1);
                    *(__half2*)&pl[(rb + g) * AKP + n * 8 + 2 * t] = __halves2half2(l0, l1);
                    splitf(s[im][n][2] * 256.0f, h0, l0);
                    splitf(s[im][n][3] * 256.0f, h1, l1);
                    *(__half2*)&ph[(rb + 8 + g) * AKP + n * 8 + 2 * t] = __halves2half2(h0, h1);
                    *(__half2*)&pl[(rb + 8 + g) * AKP + n * 8 + 2 * t] = __halves2half2(l0, l1);
                }
            }
            __syncwarp();

            // ---- O += P V  (V transposed at read via ldmatrix.trans) ----
            #pragma unroll
            for (int ks = 0; ks < 4; ks++) {
                const int kk = ks * 16;
                uint32_t ahi[2][4], alo[2][4];
                #pragma unroll
                for (int im = 0; im < 2; im++) {
                    int rb = wid * 32 + im * 16;
                    ahi[im][0] = *(const uint32_t*)&ph[(rb + g) * AKP + kk + 2 * t];
                    ahi[im][1] = *(const uint32_t*)&ph[(rb + 8 + g) * AKP + kk + 2 * t];
                    ahi[im][2] = *(const uint32_t*)&ph[(rb + g) * AKP + kk + 8 + 2 * t];
                    ahi[im][3] = *(const uint32_t*)&ph[(rb + 8 + g) * AKP + kk + 8 + 2 * t];
                    alo[im][0] = *(const uint32_t*)&pl[(rb + g) * AKP + kk + 2 * t];
                    alo[im][1] = *(const uint32_t*)&pl[(rb + 8 + g) * AKP + kk + 2 * t];
                    alo[im][2] = *(const uint32_t*)&pl[(rb + g) * AKP + kk + 8 + 2 * t];
                    alo[im][3] = *(const uint32_t*)&pl[(rb + 8 + g) * AKP + kk + 8 + 2 * t];
                }
                // lane-address for ldmatrix x4: j = lane/8 selects (k-half, dh-half)
                const int rml = kk + ((lane >> 3) & 1) * 8 + (lane & 7);
                #pragma unroll
                for (int nb = 0; nb < 4; nb++) {
                    const int cml = nb * 16 + (lane >> 4) * 8;
                    uint32_t va = sb + (uint32_t)(OVH + rml * AKP + cml) * 2u;
                    uint32_t vb_ = sb + (uint32_t)(OVL + rml * AKP + cml) * 2u;
                    uint32_t h0, h1, h2, h3, l0, l1, l2, l3;
                    ldmx4t(h0, h1, h2, h3, va);
                    ldmx4t(l0, l1, l2, l3, vb_);
                    uint32_t bh0[2] = { h0, h1 }, bh1[2] = { h2, h3 };
                    uint32_t bl0[2] = { l0, l1 }, bl1[2] = { l2, l3 };
                    #pragma unroll
                    for (int im = 0; im < 2; im++) {
                        mma16(o[im][2 * nb + 0], ahi[im], bh0);
                        mma16(o[im][2 * nb + 0], ahi[im], bl0);
                        mma16(o[im][2 * nb + 0], alo[im], bh0);
                        mma16(o[im][2 * nb + 1], ahi[im], bh1);
                        mma16(o[im][2 * nb + 1], ahi[im], bl1);
                        mma16(o[im][2 * nb + 1], alo[im], bh1);
                    }
                }
            }
        }
        __syncthreads();
    }

    // ---- epilogue: normalize (undo P x256) + write ----
    float* Ob = g_O + (size_t)b * SEQ * DIM + h * DH;
    #pragma unroll
    for (int im = 0; im < 2; im++) {
        int r0 = q0 + wid * 32 + im * 16 + g;
        int r1 = r0 + 8;
        float inv0 = 1.0f / (256.0f * l[im * 2 + 0]);
        float inv1 = 1.0f / (256.0f * l[im * 2 + 1]);
        #pragma unroll
        for (int n = 0; n < 8; n++) {
            int c = n * 8 + 2 * t;
            float2 o0 = { o[im][n][0] * inv0, o[im][n][1] * inv0 };
            float2 o1 = { o[im][n][2] * inv1, o[im][n][3] * inv1 };
            *(float2*)(Ob + (size_t)r0 * DIM + c) = o0;
            *(float2*)(Ob + (size_t)r1 * DIM + c) = o1;
        }
    }
}

// ---------------- launch ----------------
extern "C" void kernel_launch(void* const* d_in, const int* in_sizes, int n_in,
                              void* d_out, int out_size)
{
    const float* x  = (const float*)d_in[0];
    const float* WQ = (const float*)d_in[1];
    const float* WK = (const float*)d_in[2];
    const float* WV = (const float*)d_in[3];
    const float* WO = (const float*)d_in[4];
    const int*  pos = (const int*)d_in[5];
    float* out = (float*)d_out;

    cudaFuncSetAttribute(gemm_h2<0>, cudaFuncAttributeMaxDynamicSharedMemorySize, GEMM_SMEM);
    cudaFuncSetAttribute(gemm_h2<1>, cudaFuncAttributeMaxDynamicSharedMemorySize, GEMM_SMEM);
    cudaFuncSetAttribute(gemm_h2<2>, cudaFuncAttributeMaxDynamicSharedMemorySize, GEMM_SMEM);
    cudaFuncSetAttribute(gemm_h2<3>, cudaFuncAttributeMaxDynamicSharedMemorySize, GEMM_SMEM);
    cudaFuncSetAttribute(attn_h2_kernel, cudaFuncAttributeMaxDynamicSharedMemorySize, ATT_SMEM);

    rope_table_kernel<<<(SEQ * 32 + 255) / 256, 256>>>(pos);

    dim3 ggrid(DIM / 128, NROWS / 128);   // (8, 64)
    gemm_h2<0><<<ggrid, 256, GEMM_SMEM>>>(x, WQ, nullptr);
    gemm_h2<1><<<ggrid, 256, GEMM_SMEM>>>(x, WK, nullptr);
    gemm_h2<2><<<ggrid, 256, GEMM_SMEM>>>(x, WV, nullptr);

    attn_h2_kernel<<<dim3(SEQ / 128, BATCH * NHEAD), 128, ATT_SMEM>>>();

    gemm_h2<3><<<ggrid, 256, GEMM_SMEM>>>(nullptr, WO, out);
}